// round 1
// baseline (speedup 1.0000x reference)
#include <cuda_runtime.h>
#include <cuda_bf16.h>
#include <cstdint>

#define NCLS   5000
#define NV4    1250      // 5000 / 4
#define LVLS   4
#define NB     4096
#define NROWS  (NB * LVLS)   // 16384
#define BLK    256

// Scratch (device globals — no allocations allowed)
__device__ int   g_argmax[NROWS];
__device__ float g_ce[NROWS];

// ---------------------------------------------------------------------------
// Kernel 1: per-row online softmax statistics.
// One block per row (b*4 + l). Single pass over 5000 floats via float4.
// Produces: argmax (first occurrence) and ce = m + log(sum exp(x - m)) - x_t.
// ---------------------------------------------------------------------------
__global__ __launch_bounds__(BLK)
void row_stats_kernel(const float* __restrict__ y_pred,
                      const int*   __restrict__ y_true)
{
    const int row = blockIdx.x;
    const int tid = threadIdx.x;
    const float4* __restrict__ p =
        reinterpret_cast<const float4*>(y_pred + (size_t)row * NCLS);

    float m  = -1e30f;   // running max
    float s  = 0.0f;     // running sum of exp(x - m)
    int   ai = 0x7fffffff; // running argmax (global element index)

    #pragma unroll
    for (int it = 0; it < 5; ++it) {
        int i = tid + it * BLK;
        if (i < NV4) {
            float4 v = p[i];
            // first-occurrence max within the 4-vector
            float bm = v.x; int bk = 0;
            if (v.y > bm) { bm = v.y; bk = 1; }
            if (v.z > bm) { bm = v.z; bk = 2; }
            if (v.w > bm) { bm = v.w; bk = 3; }
            if (bm > m) {                      // rare after warm-up (~ln N times)
                s *= __expf(m - bm);
                m  = bm;
                ai = i * 4 + bk;
            }
            s += __expf(v.x - m) + __expf(v.y - m) +
                 __expf(v.z - m) + __expf(v.w - m);
        }
    }

    // --- warp reduction of (m, s, ai) ---
    const unsigned full = 0xffffffffu;
    #pragma unroll
    for (int off = 16; off; off >>= 1) {
        float om  = __shfl_down_sync(full, m,  off);
        float os  = __shfl_down_sync(full, s,  off);
        int   oai = __shfl_down_sync(full, ai, off);
        bool take = (om > m) || (om == m && oai < ai);
        int  nai  = take ? oai : ai;
        float nm  = fmaxf(m, om);
        s  = s * __expf(m - nm) + os * __expf(om - nm);
        m  = nm;
        ai = nai;
    }

    // --- cross-warp reduction (8 warps) ---
    __shared__ float sh_m[8];
    __shared__ float sh_s[8];
    __shared__ int   sh_ai[8];
    const int wid = tid >> 5, lane = tid & 31;
    if (lane == 0) { sh_m[wid] = m; sh_s[wid] = s; sh_ai[wid] = ai; }
    __syncthreads();

    if (wid == 0) {
        m  = (lane < 8) ? sh_m[lane]  : -1e30f;
        s  = (lane < 8) ? sh_s[lane]  : 0.0f;
        ai = (lane < 8) ? sh_ai[lane] : 0x7fffffff;
        #pragma unroll
        for (int off = 4; off; off >>= 1) {
            float om  = __shfl_down_sync(full, m,  off);
            float os  = __shfl_down_sync(full, s,  off);
            int   oai = __shfl_down_sync(full, ai, off);
            bool take = (om > m) || (om == m && oai < ai);
            int  nai  = take ? oai : ai;
            float nm  = fmaxf(m, om);
            s  = s * __expf(m - nm) + os * __expf(om - nm);
            m  = nm;
            ai = nai;
        }
        if (lane == 0) {
            g_argmax[row] = ai;
            int t = __ldg(y_true + row);
            float xt = __ldg(y_pred + (size_t)row * NCLS + t);
            g_ce[row] = m + __logf(s) - xt;
        }
    }
}

// ---------------------------------------------------------------------------
// Kernel 2: final reduction.
// loss = sum_{j=1..3} w[j] * ( count(H[idx[:,j-1],idx[:,j]] != 1) * e
//                              + mean_b ce[b,j] )
// ---------------------------------------------------------------------------
__global__ __launch_bounds__(1024)
void final_kernel(const float* __restrict__ H, float* __restrict__ out)
{
    const int tid = threadIdx.x;
    float ce1 = 0.f, ce2 = 0.f, ce3 = 0.f;
    int   c1 = 0, c2 = 0, c3 = 0;

    for (int b = tid; b < NB; b += 1024) {
        int base = b * LVLS;
        int i0 = g_argmax[base + 0];
        int i1 = g_argmax[base + 1];
        int i2 = g_argmax[base + 2];
        int i3 = g_argmax[base + 3];
        ce1 += g_ce[base + 1];
        ce2 += g_ce[base + 2];
        ce3 += g_ce[base + 3];
        c1 += (__ldg(H + (size_t)i0 * NCLS + i1) != 1.0f);
        c2 += (__ldg(H + (size_t)i1 * NCLS + i2) != 1.0f);
        c3 += (__ldg(H + (size_t)i2 * NCLS + i3) != 1.0f);
    }

    // warp reduce
    const unsigned full = 0xffffffffu;
    #pragma unroll
    for (int off = 16; off; off >>= 1) {
        ce1 += __shfl_down_sync(full, ce1, off);
        ce2 += __shfl_down_sync(full, ce2, off);
        ce3 += __shfl_down_sync(full, ce3, off);
        c1  += __shfl_down_sync(full, c1,  off);
        c2  += __shfl_down_sync(full, c2,  off);
        c3  += __shfl_down_sync(full, c3,  off);
    }

    __shared__ float s_ce[3][32];
    __shared__ int   s_c[3][32];
    const int wid = tid >> 5, lane = tid & 31;
    if (lane == 0) {
        s_ce[0][wid] = ce1; s_ce[1][wid] = ce2; s_ce[2][wid] = ce3;
        s_c[0][wid]  = c1;  s_c[1][wid]  = c2;  s_c[2][wid]  = c3;
    }
    __syncthreads();

    if (wid == 0) {
        ce1 = s_ce[0][lane]; ce2 = s_ce[1][lane]; ce3 = s_ce[2][lane];
        c1  = s_c[0][lane];  c2  = s_c[1][lane];  c3  = s_c[2][lane];
        #pragma unroll
        for (int off = 16; off; off >>= 1) {
            ce1 += __shfl_down_sync(full, ce1, off);
            ce2 += __shfl_down_sync(full, ce2, off);
            ce3 += __shfl_down_sync(full, ce3, off);
            c1  += __shfl_down_sync(full, c1,  off);
            c2  += __shfl_down_sync(full, c2,  off);
            c3  += __shfl_down_sync(full, c3,  off);
        }
        if (lane == 0) {
            const float E  = 2.718281828459045f;
            const float iB = 1.0f / (float)NB;
            float loss = 0.25f * ((float)c1 * E + ce1 * iB)
                       + 0.15f * ((float)c2 * E + ce2 * iB)
                       + 0.10f * ((float)c3 * E + ce3 * iB);
            out[0] = loss;
        }
    }
}

// ---------------------------------------------------------------------------
extern "C" void kernel_launch(void* const* d_in, const int* in_sizes, int n_in,
                              void* d_out, int out_size)
{
    // Identify inputs by size (robust to metadata ordering):
    //   y_pred : 4096*4*5000 = 81,920,000 floats
    //   y_true : 16,384 ints
    //   H      : 5000*5000 = 25,000,000 floats
    const float* y_pred = nullptr;
    const int*   y_true = nullptr;
    const float* H      = nullptr;
    for (int i = 0; i < n_in; ++i) {
        if (in_sizes[i] == NROWS * NCLS)      y_pred = (const float*)d_in[i];
        else if (in_sizes[i] == NROWS)        y_true = (const int*)d_in[i];
        else if (in_sizes[i] == NCLS * NCLS)  H      = (const float*)d_in[i];
    }

    row_stats_kernel<<<NROWS, BLK>>>(y_pred, y_true);
    final_kernel<<<1, 1024>>>(H, (float*)d_out);
}

// round 4
// speedup vs baseline: 1.1236x; 1.1236x over previous
#include <cuda_runtime.h>
#include <cuda_bf16.h>
#include <cstdint>

#define NCLS   5000
#define NV4    1250      // 5000 / 4
#define LVLS   4
#define NB     4096
#define NROWS  (NB * LVLS)   // 16384
#define BLK    256
#define FBLKS  16            // gather-phase blocks (16*256 = 4096 = NB)

// Scratch (device globals — no allocations, no host API lookups, no atomics)
__device__ int   g_argmax[NROWS];
__device__ float g_ce[NROWS];
__device__ float g_part_ce[FBLKS][3];
__device__ int   g_part_cnt[FBLKS][3];

// ---------------------------------------------------------------------------
// Kernel 1: per-row online softmax statistics.
// One block per row. Loads front-batched (5x float4, evict-first) for MLP.
// ---------------------------------------------------------------------------
__global__ __launch_bounds__(BLK)
void row_stats_kernel(const float* __restrict__ y_pred,
                      const int*   __restrict__ y_true)
{
    const int row = blockIdx.x;
    const int tid = threadIdx.x;
    const float4* __restrict__ p =
        reinterpret_cast<const float4*>(y_pred + (size_t)row * NCLS);

    // ---- front-batched loads: 5 independent LDG.128 in flight ----
    float4 v[5];
    #pragma unroll
    for (int it = 0; it < 5; ++it) {
        int i = tid + it * BLK;
        if (i < NV4) v[it] = __ldcs(p + i);
        else         v[it] = make_float4(-1e30f, -1e30f, -1e30f, -1e30f);
    }

    float m  = -1e30f;     // running max
    float s  = 0.0f;       // running sum of exp(x - m)
    int   ai = 0x7fffffff; // running argmax (global element index)

    #pragma unroll
    for (int it = 0; it < 5; ++it) {
        int i = tid + it * BLK;
        float4 q = v[it];
        float bm = q.x; int bk = 0;
        if (q.y > bm) { bm = q.y; bk = 1; }
        if (q.z > bm) { bm = q.z; bk = 2; }
        if (q.w > bm) { bm = q.w; bk = 3; }
        if (bm > m) {                       // rare after warm-up
            s *= __expf(m - bm);
            m  = bm;
            ai = i * 4 + bk;
        }
        s += __expf(q.x - m) + __expf(q.y - m) +
             __expf(q.z - m) + __expf(q.w - m);
    }

    // --- warp reduction of (m, s, ai) ---
    const unsigned full = 0xffffffffu;
    #pragma unroll
    for (int off = 16; off; off >>= 1) {
        float om  = __shfl_down_sync(full, m,  off);
        float os  = __shfl_down_sync(full, s,  off);
        int   oai = __shfl_down_sync(full, ai, off);
        bool take = (om > m) || (om == m && oai < ai);
        int  nai  = take ? oai : ai;
        float nm  = fmaxf(m, om);
        s  = s * __expf(m - nm) + os * __expf(om - nm);
        m  = nm;
        ai = nai;
    }

    // --- cross-warp reduction (8 warps) ---
    __shared__ float sh_m[8];
    __shared__ float sh_s[8];
    __shared__ int   sh_ai[8];
    const int wid = tid >> 5, lane = tid & 31;
    if (lane == 0) { sh_m[wid] = m; sh_s[wid] = s; sh_ai[wid] = ai; }
    __syncthreads();

    if (wid == 0) {
        m  = (lane < 8) ? sh_m[lane]  : -1e30f;
        s  = (lane < 8) ? sh_s[lane]  : 0.0f;
        ai = (lane < 8) ? sh_ai[lane] : 0x7fffffff;
        #pragma unroll
        for (int off = 4; off; off >>= 1) {
            float om  = __shfl_down_sync(full, m,  off);
            float os  = __shfl_down_sync(full, s,  off);
            int   oai = __shfl_down_sync(full, ai, off);
            bool take = (om > m) || (om == m && oai < ai);
            int  nai  = take ? oai : ai;
            float nm  = fmaxf(m, om);
            s  = s * __expf(m - nm) + os * __expf(om - nm);
            m  = nm;
            ai = nai;
        }
        if (lane == 0) {
            g_argmax[row] = ai;
            int t = __ldg(y_true + row);
            float xt = __ldg(y_pred + (size_t)row * NCLS + t);
            g_ce[row] = m + __logf(s) - xt;
        }
    }
}

// ---------------------------------------------------------------------------
// Kernel 2: gather + per-block partial reduce. 16 blocks x 256 threads,
// one thread per batch element. Plain stores of per-block partials.
// ---------------------------------------------------------------------------
__global__ __launch_bounds__(BLK)
void gather_kernel(const float* __restrict__ H)
{
    const int tid  = threadIdx.x;
    const int b    = blockIdx.x * BLK + tid;   // 0..4095
    const int base = b * LVLS;

    int i0 = g_argmax[base + 0];
    int i1 = g_argmax[base + 1];
    int i2 = g_argmax[base + 2];
    int i3 = g_argmax[base + 3];
    float ce1 = g_ce[base + 1];
    float ce2 = g_ce[base + 2];
    float ce3 = g_ce[base + 3];
    int c1 = (__ldg(H + (size_t)i0 * NCLS + i1) != 1.0f);
    int c2 = (__ldg(H + (size_t)i1 * NCLS + i2) != 1.0f);
    int c3 = (__ldg(H + (size_t)i2 * NCLS + i3) != 1.0f);

    // warp reduce
    const unsigned full = 0xffffffffu;
    #pragma unroll
    for (int off = 16; off; off >>= 1) {
        ce1 += __shfl_down_sync(full, ce1, off);
        ce2 += __shfl_down_sync(full, ce2, off);
        ce3 += __shfl_down_sync(full, ce3, off);
        c1  += __shfl_down_sync(full, c1,  off);
        c2  += __shfl_down_sync(full, c2,  off);
        c3  += __shfl_down_sync(full, c3,  off);
    }

    __shared__ float s_ce[3][8];
    __shared__ int   s_c[3][8];
    const int wid = tid >> 5, lane = tid & 31;
    if (lane == 0) {
        s_ce[0][wid] = ce1; s_ce[1][wid] = ce2; s_ce[2][wid] = ce3;
        s_c[0][wid]  = c1;  s_c[1][wid]  = c2;  s_c[2][wid]  = c3;
    }
    __syncthreads();

    if (wid == 0) {
        ce1 = (lane < 8) ? s_ce[0][lane] : 0.f;
        ce2 = (lane < 8) ? s_ce[1][lane] : 0.f;
        ce3 = (lane < 8) ? s_ce[2][lane] : 0.f;
        c1  = (lane < 8) ? s_c[0][lane]  : 0;
        c2  = (lane < 8) ? s_c[1][lane]  : 0;
        c3  = (lane < 8) ? s_c[2][lane]  : 0;
        #pragma unroll
        for (int off = 4; off; off >>= 1) {
            ce1 += __shfl_down_sync(full, ce1, off);
            ce2 += __shfl_down_sync(full, ce2, off);
            ce3 += __shfl_down_sync(full, ce3, off);
            c1  += __shfl_down_sync(full, c1,  off);
            c2  += __shfl_down_sync(full, c2,  off);
            c3  += __shfl_down_sync(full, c3,  off);
        }
        if (lane == 0) {
            g_part_ce[blockIdx.x][0]  = ce1;
            g_part_ce[blockIdx.x][1]  = ce2;
            g_part_ce[blockIdx.x][2]  = ce3;
            g_part_cnt[blockIdx.x][0] = c1;
            g_part_cnt[blockIdx.x][1] = c2;
            g_part_cnt[blockIdx.x][2] = c3;
        }
    }
}

// ---------------------------------------------------------------------------
// Kernel 3: tiny finalize — one warp sums the 16 partials, writes the scalar.
// ---------------------------------------------------------------------------
__global__ __launch_bounds__(32)
void finalize_kernel(float* __restrict__ out)
{
    const int lane = threadIdx.x;
    float ce1 = 0.f, ce2 = 0.f, ce3 = 0.f;
    int   c1 = 0, c2 = 0, c3 = 0;
    if (lane < FBLKS) {
        ce1 = g_part_ce[lane][0];
        ce2 = g_part_ce[lane][1];
        ce3 = g_part_ce[lane][2];
        c1  = g_part_cnt[lane][0];
        c2  = g_part_cnt[lane][1];
        c3  = g_part_cnt[lane][2];
    }
    const unsigned full = 0xffffffffu;
    #pragma unroll
    for (int off = 8; off; off >>= 1) {
        ce1 += __shfl_down_sync(full, ce1, off);
        ce2 += __shfl_down_sync(full, ce2, off);
        ce3 += __shfl_down_sync(full, ce3, off);
        c1  += __shfl_down_sync(full, c1,  off);
        c2  += __shfl_down_sync(full, c2,  off);
        c3  += __shfl_down_sync(full, c3,  off);
    }
    if (lane == 0) {
        const float E  = 2.718281828459045f;
        const float iB = 1.0f / (float)NB;
        float loss = 0.25f * ((float)c1 * E + ce1 * iB)
                   + 0.15f * ((float)c2 * E + ce2 * iB)
                   + 0.10f * ((float)c3 * E + ce3 * iB);
        out[0] = loss;
    }
}

// ---------------------------------------------------------------------------
extern "C" void kernel_launch(void* const* d_in, const int* in_sizes, int n_in,
                              void* d_out, int out_size)
{
    const float* y_pred = nullptr;
    const int*   y_true = nullptr;
    const float* H      = nullptr;
    for (int i = 0; i < n_in; ++i) {
        if (in_sizes[i] == NROWS * NCLS)      y_pred = (const float*)d_in[i];
        else if (in_sizes[i] == NROWS)        y_true = (const int*)d_in[i];
        else if (in_sizes[i] == NCLS * NCLS)  H      = (const float*)d_in[i];
    }

    row_stats_kernel<<<NROWS, BLK>>>(y_pred, y_true);
    gather_kernel<<<FBLKS, BLK>>>(H);
    finalize_kernel<<<1, 32>>>((float*)d_out);
}

// round 5
// speedup vs baseline: 1.1933x; 1.0620x over previous
#include <cuda_runtime.h>
#include <cuda_bf16.h>
#include <cstdint>

#define NCLS   5000
#define NV4    1250      // 5000 / 4
#define LVLS   4
#define NB     4096
#define NROWS  (NB * LVLS)   // 16384
#define BLK    256
#define FBLKS  16            // gather-phase blocks (16*256 = 4096 = NB)

#define L2E    1.4426950408889634f   // log2(e)
#define LN2    0.6931471805599453f

// Scratch (device globals — no allocations, no host API lookups, no atomics)
__device__ int   g_argmax[NROWS];
__device__ float g_ce[NROWS];
__device__ float g_part_ce[FBLKS][3];
__device__ int   g_part_cnt[FBLKS][3];

__device__ __forceinline__ float ex2(float x) {
    float y;
    asm("ex2.approx.ftz.f32 %0, %1;" : "=f"(y) : "f"(x));
    return y;
}

// ---------------------------------------------------------------------------
// Kernel 1: per-row softmax stats, minimal-instruction form.
// Phase A: pure-FMNMX local max. Phase B: FFMA(imm)+EX2+FADD sum.
// Argmax: equality rescan by the (rare) threads holding the block max.
// ---------------------------------------------------------------------------
__global__ __launch_bounds__(BLK)
void row_stats_kernel(const float* __restrict__ y_pred,
                      const int*   __restrict__ y_true)
{
    const int row = blockIdx.x;
    const int tid = threadIdx.x;
    const float4* __restrict__ p =
        reinterpret_cast<const float4*>(y_pred + (size_t)row * NCLS);

    // ---- front-batched loads: 5 independent LDG.128, evict-first ----
    float4 v[5];
    #pragma unroll
    for (int it = 0; it < 5; ++it) {
        int i = tid + it * BLK;
        if (it < 4 || i < NV4) v[it] = __ldcs(p + i);
        else                   v[it] = make_float4(-1e30f, -1e30f, -1e30f, -1e30f);
    }

    // ---- Phase A: local max (pure FMNMX tree, no indices) ----
    float mloc = fmaxf(fmaxf(v[0].x, v[0].y), fmaxf(v[0].z, v[0].w));
    #pragma unroll
    for (int it = 1; it < 5; ++it) {
        float a = fmaxf(v[it].x, v[it].y);
        float b = fmaxf(v[it].z, v[it].w);
        mloc = fmaxf(mloc, fmaxf(a, b));
    }

    // ---- Phase B: sum exp2(x*L2E - mloc*L2E), 4 accumulators ----
    const float ml = mloc * L2E;
    float s0 = 0.f, s1 = 0.f, s2 = 0.f, s3 = 0.f;
    #pragma unroll
    for (int it = 0; it < 5; ++it) {
        s0 += ex2(fmaf(v[it].x, L2E, -ml));
        s1 += ex2(fmaf(v[it].y, L2E, -ml));
        s2 += ex2(fmaf(v[it].z, L2E, -ml));
        s3 += ex2(fmaf(v[it].w, L2E, -ml));
    }
    float s = (s0 + s1) + (s2 + s3);
    float m = mloc;

    // ---- warp reduction of (m, s) ----
    const unsigned full = 0xffffffffu;
    #pragma unroll
    for (int off = 16; off; off >>= 1) {
        float om = __shfl_down_sync(full, m, off);
        float os = __shfl_down_sync(full, s, off);
        float nm = fmaxf(m, om);
        s = s * ex2((m - nm) * L2E) + os * ex2((om - nm) * L2E);
        m = nm;
    }

    // ---- cross-warp reduction (8 warps) ----
    __shared__ float sh_m[8];
    __shared__ float sh_s[8];
    __shared__ float sh_M;
    __shared__ float sh_S;
    const int wid = tid >> 5, lane = tid & 31;
    if (lane == 0) { sh_m[wid] = m; sh_s[wid] = s; }
    __syncthreads();

    if (wid == 0) {
        m = (lane < 8) ? sh_m[lane] : -1e30f;
        s = (lane < 8) ? sh_s[lane] : 0.0f;
        #pragma unroll
        for (int off = 4; off; off >>= 1) {
            float om = __shfl_down_sync(full, m, off);
            float os = __shfl_down_sync(full, s, off);
            float nm = fmaxf(m, om);
            s = s * ex2((m - nm) * L2E) + os * ex2((om - nm) * L2E);
            m = nm;
        }
        if (lane == 0) { sh_M = m; sh_S = s; }
    }
    __syncthreads();

    // ---- argmax: equality rescan by threads holding the block max ----
    const float M = sh_M;
    int idx = 0x7fffffff;
    if (mloc == M) {   // rare: typically one thread per block
        #pragma unroll
        for (int it = 0; it < 5; ++it) {
            int gi = (tid + it * BLK) << 2;
            if (v[it].x == M) idx = min(idx, gi + 0);
            if (v[it].y == M) idx = min(idx, gi + 1);
            if (v[it].z == M) idx = min(idx, gi + 2);
            if (v[it].w == M) idx = min(idx, gi + 3);
        }
    }
    idx = __reduce_min_sync(full, idx);

    __shared__ int sh_idx[8];
    if (lane == 0) sh_idx[wid] = idx;
    __syncthreads();

    if (tid == 0) {
        int best = sh_idx[0];
        #pragma unroll
        for (int w = 1; w < 8; ++w) best = min(best, sh_idx[w]);
        g_argmax[row] = best;
        int t = __ldg(y_true + row);
        float xt = __ldg(y_pred + (size_t)row * NCLS + t);
        // ce = M + ln(S) - xt
        g_ce[row] = fmaf(LN2, __log2f(sh_S), M) - xt;
    }
}

// ---------------------------------------------------------------------------
// Kernel 2: gather + per-block partial reduce. 16 blocks x 256 threads.
// ---------------------------------------------------------------------------
__global__ __launch_bounds__(BLK)
void gather_kernel(const float* __restrict__ H)
{
    const int tid  = threadIdx.x;
    const int b    = blockIdx.x * BLK + tid;   // 0..4095
    const int base = b * LVLS;

    int i0 = g_argmax[base + 0];
    int i1 = g_argmax[base + 1];
    int i2 = g_argmax[base + 2];
    int i3 = g_argmax[base + 3];
    float ce1 = g_ce[base + 1];
    float ce2 = g_ce[base + 2];
    float ce3 = g_ce[base + 3];
    int c1 = (__ldg(H + (size_t)i0 * NCLS + i1) != 1.0f);
    int c2 = (__ldg(H + (size_t)i1 * NCLS + i2) != 1.0f);
    int c3 = (__ldg(H + (size_t)i2 * NCLS + i3) != 1.0f);

    const unsigned full = 0xffffffffu;
    #pragma unroll
    for (int off = 16; off; off >>= 1) {
        ce1 += __shfl_down_sync(full, ce1, off);
        ce2 += __shfl_down_sync(full, ce2, off);
        ce3 += __shfl_down_sync(full, ce3, off);
    }
    c1 = __reduce_add_sync(full, c1);
    c2 = __reduce_add_sync(full, c2);
    c3 = __reduce_add_sync(full, c3);

    __shared__ float s_ce[3][8];
    __shared__ int   s_c[3][8];
    const int wid = tid >> 5, lane = tid & 31;
    if (lane == 0) {
        s_ce[0][wid] = ce1; s_ce[1][wid] = ce2; s_ce[2][wid] = ce3;
        s_c[0][wid]  = c1;  s_c[1][wid]  = c2;  s_c[2][wid]  = c3;
    }
    __syncthreads();

    if (tid == 0) {
        float a1 = 0.f, a2 = 0.f, a3 = 0.f;
        int   b1 = 0, b2 = 0, b3 = 0;
        #pragma unroll
        for (int w = 0; w < 8; ++w) {
            a1 += s_ce[0][w]; a2 += s_ce[1][w]; a3 += s_ce[2][w];
            b1 += s_c[0][w];  b2 += s_c[1][w];  b3 += s_c[2][w];
        }
        g_part_ce[blockIdx.x][0]  = a1;
        g_part_ce[blockIdx.x][1]  = a2;
        g_part_ce[blockIdx.x][2]  = a3;
        g_part_cnt[blockIdx.x][0] = b1;
        g_part_cnt[blockIdx.x][1] = b2;
        g_part_cnt[blockIdx.x][2] = b3;
    }
}

// ---------------------------------------------------------------------------
// Kernel 3: tiny finalize — one warp sums the 16 partials, writes the scalar.
// ---------------------------------------------------------------------------
__global__ __launch_bounds__(32)
void finalize_kernel(float* __restrict__ out)
{
    const int lane = threadIdx.x;
    float ce1 = 0.f, ce2 = 0.f, ce3 = 0.f;
    int   c1 = 0, c2 = 0, c3 = 0;
    if (lane < FBLKS) {
        ce1 = g_part_ce[lane][0];
        ce2 = g_part_ce[lane][1];
        ce3 = g_part_ce[lane][2];
        c1  = g_part_cnt[lane][0];
        c2  = g_part_cnt[lane][1];
        c3  = g_part_cnt[lane][2];
    }
    const unsigned full = 0xffffffffu;
    #pragma unroll
    for (int off = 8; off; off >>= 1) {
        ce1 += __shfl_down_sync(full, ce1, off);
        ce2 += __shfl_down_sync(full, ce2, off);
        ce3 += __shfl_down_sync(full, ce3, off);
        c1  += __shfl_down_sync(full, c1,  off);
        c2  += __shfl_down_sync(full, c2,  off);
        c3  += __shfl_down_sync(full, c3,  off);
    }
    if (lane == 0) {
        const float E  = 2.718281828459045f;
        const float iB = 1.0f / (float)NB;
        float loss = 0.25f * ((float)c1 * E + ce1 * iB)
                   + 0.15f * ((float)c2 * E + ce2 * iB)
                   + 0.10f * ((float)c3 * E + ce3 * iB);
        out[0] = loss;
    }
}

// ---------------------------------------------------------------------------
extern "C" void kernel_launch(void* const* d_in, const int* in_sizes, int n_in,
                              void* d_out, int out_size)
{
    const float* y_pred = nullptr;
    const int*   y_true = nullptr;
    const float* H      = nullptr;
    for (int i = 0; i < n_in; ++i) {
        if (in_sizes[i] == NROWS * NCLS)      y_pred = (const float*)d_in[i];
        else if (in_sizes[i] == NROWS)        y_true = (const int*)d_in[i];
        else if (in_sizes[i] == NCLS * NCLS)  H      = (const float*)d_in[i];
    }

    row_stats_kernel<<<NROWS, BLK>>>(y_pred, y_true);
    gather_kernel<<<FBLKS, BLK>>>(H);
    finalize_kernel<<<1, 32>>>((float*)d_out);
}

// round 7
// speedup vs baseline: 1.2255x; 1.0270x over previous
#include <cuda_runtime.h>
#include <cuda_bf16.h>
#include <cstdint>

#define NCLS   5000
#define NV4    1250      // 5000 / 4
#define LVLS   4
#define NB     4096
#define NROWS  (NB * LVLS)   // 16384
#define BLK    256
#define RPB    4             // rows per block (software pipeline depth)
#define GRID1  (NROWS / RPB) // 4096
#define FBLKS  16

#define L2E    1.4426950408889634f   // log2(e)
#define LN2    0.6931471805599453f

// Scratch (device globals — no allocations, no host API lookups, no atomics)
__device__ int   g_argmax[NROWS];
__device__ float g_ce[NROWS];
__device__ float g_part_ce[FBLKS][3];
__device__ int   g_part_cnt[FBLKS][3];

__device__ __forceinline__ float ex2(float x) {
    float y;
    asm("ex2.approx.ftz.f32 %0, %1;" : "=f"(y) : "f"(x));
    return y;
}

// ---------------------------------------------------------------------------
// Kernel 1: per-row softmax stats, 4 rows per block, register double-buffered.
// Prefetch of row r+1 is issued BEFORE the reduction tail of row r, so the
// memory system never idles during barriers/reductions.
// ---------------------------------------------------------------------------
__global__ __launch_bounds__(BLK, 4)
void row_stats_kernel(const float* __restrict__ y_pred,
                      const int*   __restrict__ y_true)
{
    const int tid  = threadIdx.x;
    const int row0 = blockIdx.x * RPB;

    __shared__ float sh_xt[RPB];
    __shared__ float sh_m[8];
    __shared__ float sh_s[8];
    __shared__ float sh_M, sh_S;
    __shared__ int   sh_idx[8];

    // Resolve all target logits up front (dependent chain off the critical tail)
    if (tid < RPB) {
        int t = __ldg(y_true + row0 + tid);
        sh_xt[tid] = __ldg(y_pred + (size_t)(row0 + tid) * NCLS + t);
    }

    float4 buf[2][5];

    // Prefetch row 0
    {
        const float4* __restrict__ p =
            reinterpret_cast<const float4*>(y_pred + (size_t)row0 * NCLS);
        #pragma unroll
        for (int it = 0; it < 5; ++it) {
            int i = tid + it * BLK;
            if (it < 4 || i < NV4) buf[0][it] = __ldcs(p + i);
            else buf[0][it] = make_float4(-1e30f, -1e30f, -1e30f, -1e30f);
        }
    }

    const unsigned full = 0xffffffffu;
    const int wid = tid >> 5, lane = tid & 31;

    #pragma unroll
    for (int r = 0; r < RPB; ++r) {
        float4* v = buf[r & 1];

        // ---- prefetch next row (loads fly across the barriers below) ----
        if (r + 1 < RPB) {
            const float4* __restrict__ pn =
                reinterpret_cast<const float4*>(y_pred + (size_t)(row0 + r + 1) * NCLS);
            float4* w = buf[(r + 1) & 1];
            #pragma unroll
            for (int it = 0; it < 5; ++it) {
                int i = tid + it * BLK;
                if (it < 4 || i < NV4) w[it] = __ldcs(pn + i);
                else w[it] = make_float4(-1e30f, -1e30f, -1e30f, -1e30f);
            }
        }

        // ---- Phase A: local max (pure FMNMX tree) ----
        float mloc = fmaxf(fmaxf(v[0].x, v[0].y), fmaxf(v[0].z, v[0].w));
        #pragma unroll
        for (int it = 1; it < 5; ++it)
            mloc = fmaxf(mloc, fmaxf(fmaxf(v[it].x, v[it].y),
                                     fmaxf(v[it].z, v[it].w)));

        // ---- Phase B: sum exp2(x*L2E - ml), 4 accumulators ----
        const float ml = mloc * L2E;
        float s0 = 0.f, s1 = 0.f, s2 = 0.f, s3 = 0.f;
        #pragma unroll
        for (int it = 0; it < 5; ++it) {
            s0 += ex2(fmaf(v[it].x, L2E, -ml));
            s1 += ex2(fmaf(v[it].y, L2E, -ml));
            s2 += ex2(fmaf(v[it].z, L2E, -ml));
            s3 += ex2(fmaf(v[it].w, L2E, -ml));
        }
        float s = (s0 + s1) + (s2 + s3);
        float m = mloc;

        // ---- warp reduce (m, s) ----
        #pragma unroll
        for (int off = 16; off; off >>= 1) {
            float om = __shfl_down_sync(full, m, off);
            float os = __shfl_down_sync(full, s, off);
            float nm = fmaxf(m, om);
            s = s * ex2((m - nm) * L2E) + os * ex2((om - nm) * L2E);
            m = nm;
        }
        if (lane == 0) { sh_m[wid] = m; sh_s[wid] = s; }
        __syncthreads();

        if (wid == 0) {
            m = (lane < 8) ? sh_m[lane] : -1e30f;
            s = (lane < 8) ? sh_s[lane] : 0.0f;
            #pragma unroll
            for (int off = 4; off; off >>= 1) {
                float om = __shfl_down_sync(full, m, off);
                float os = __shfl_down_sync(full, s, off);
                float nm = fmaxf(m, om);
                s = s * ex2((m - nm) * L2E) + os * ex2((om - nm) * L2E);
                m = nm;
            }
            if (lane == 0) { sh_M = m; sh_S = s; }
        }
        __syncthreads();

        // ---- argmax: equality rescan by threads holding the block max ----
        // Sentinel MUST stay INT_MAX as a signed int end-to-end (R6 bug:
        // unsigned 0xffffffff cast to int became -1 and won the min).
        const float M = sh_M;
        int idx = 0x7fffffff;
        if (mloc == M) {
            #pragma unroll
            for (int it = 0; it < 5; ++it) {
                int gi = (tid + it * BLK) << 2;
                if (v[it].x == M) idx = min(idx, gi + 0);
                if (v[it].y == M) idx = min(idx, gi + 1);
                if (v[it].z == M) idx = min(idx, gi + 2);
                if (v[it].w == M) idx = min(idx, gi + 3);
            }
        }
        idx = __reduce_min_sync(full, idx);
        if (lane == 0) sh_idx[wid] = idx;
        __syncthreads();

        if (tid == 0) {
            int best = sh_idx[0];
            #pragma unroll
            for (int w = 1; w < 8; ++w) best = min(best, sh_idx[w]);
            g_argmax[row0 + r] = best;
            g_ce[row0 + r] = fmaf(LN2, __log2f(sh_S), sh_M) - sh_xt[r];
        }
    }
}

// ---------------------------------------------------------------------------
// Kernel 2: gather + per-block partial reduce. 16 blocks x 256 threads.
// ---------------------------------------------------------------------------
__global__ __launch_bounds__(BLK)
void gather_kernel(const float* __restrict__ H)
{
    const int tid  = threadIdx.x;
    const int b    = blockIdx.x * BLK + tid;   // 0..4095
    const int base = b * LVLS;

    int i0 = g_argmax[base + 0];
    int i1 = g_argmax[base + 1];
    int i2 = g_argmax[base + 2];
    int i3 = g_argmax[base + 3];
    float ce1 = g_ce[base + 1];
    float ce2 = g_ce[base + 2];
    float ce3 = g_ce[base + 3];
    int c1 = (__ldg(H + (size_t)i0 * NCLS + i1) != 1.0f);
    int c2 = (__ldg(H + (size_t)i1 * NCLS + i2) != 1.0f);
    int c3 = (__ldg(H + (size_t)i2 * NCLS + i3) != 1.0f);

    const unsigned full = 0xffffffffu;
    #pragma unroll
    for (int off = 16; off; off >>= 1) {
        ce1 += __shfl_down_sync(full, ce1, off);
        ce2 += __shfl_down_sync(full, ce2, off);
        ce3 += __shfl_down_sync(full, ce3, off);
    }
    c1 = __reduce_add_sync(full, c1);
    c2 = __reduce_add_sync(full, c2);
    c3 = __reduce_add_sync(full, c3);

    __shared__ float s_ce[3][8];
    __shared__ int   s_c[3][8];
    const int wid = tid >> 5, lane = tid & 31;
    if (lane == 0) {
        s_ce[0][wid] = ce1; s_ce[1][wid] = ce2; s_ce[2][wid] = ce3;
        s_c[0][wid]  = c1;  s_c[1][wid]  = c2;  s_c[2][wid]  = c3;
    }
    __syncthreads();

    if (tid == 0) {
        float a1 = 0.f, a2 = 0.f, a3 = 0.f;
        int   b1 = 0, b2 = 0, b3 = 0;
        #pragma unroll
        for (int w = 0; w < 8; ++w) {
            a1 += s_ce[0][w]; a2 += s_ce[1][w]; a3 += s_ce[2][w];
            b1 += s_c[0][w];  b2 += s_c[1][w];  b3 += s_c[2][w];
        }
        g_part_ce[blockIdx.x][0]  = a1;
        g_part_ce[blockIdx.x][1]  = a2;
        g_part_ce[blockIdx.x][2]  = a3;
        g_part_cnt[blockIdx.x][0] = b1;
        g_part_cnt[blockIdx.x][1] = b2;
        g_part_cnt[blockIdx.x][2] = b3;
    }
}

// ---------------------------------------------------------------------------
// Kernel 3: tiny finalize — one warp sums the 16 partials, writes the scalar.
// ---------------------------------------------------------------------------
__global__ __launch_bounds__(32)
void finalize_kernel(float* __restrict__ out)
{
    const int lane = threadIdx.x;
    float ce1 = 0.f, ce2 = 0.f, ce3 = 0.f;
    int   c1 = 0, c2 = 0, c3 = 0;
    if (lane < FBLKS) {
        ce1 = g_part_ce[lane][0];
        ce2 = g_part_ce[lane][1];
        ce3 = g_part_ce[lane][2];
        c1  = g_part_cnt[lane][0];
        c2  = g_part_cnt[lane][1];
        c3  = g_part_cnt[lane][2];
    }
    const unsigned full = 0xffffffffu;
    #pragma unroll
    for (int off = 8; off; off >>= 1) {
        ce1 += __shfl_down_sync(full, ce1, off);
        ce2 += __shfl_down_sync(full, ce2, off);
        ce3 += __shfl_down_sync(full, ce3, off);
        c1  += __shfl_down_sync(full, c1,  off);
        c2  += __shfl_down_sync(full, c2,  off);
        c3  += __shfl_down_sync(full, c3,  off);
    }
    if (lane == 0) {
        const float E  = 2.718281828459045f;
        const float iB = 1.0f / (float)NB;
        float loss = 0.25f * ((float)c1 * E + ce1 * iB)
                   + 0.15f * ((float)c2 * E + ce2 * iB)
                   + 0.10f * ((float)c3 * E + ce3 * iB);
        out[0] = loss;
    }
}

// ---------------------------------------------------------------------------
extern "C" void kernel_launch(void* const* d_in, const int* in_sizes, int n_in,
                              void* d_out, int out_size)
{
    const float* y_pred = nullptr;
    const int*   y_true = nullptr;
    const float* H      = nullptr;
    for (int i = 0; i < n_in; ++i) {
        if (in_sizes[i] == NROWS * NCLS)      y_pred = (const float*)d_in[i];
        else if (in_sizes[i] == NROWS)        y_true = (const int*)d_in[i];
        else if (in_sizes[i] == NCLS * NCLS)  H      = (const float*)d_in[i];
    }

    row_stats_kernel<<<GRID1, BLK>>>(y_pred, y_true);
    gather_kernel<<<FBLKS, BLK>>>(H);
    finalize_kernel<<<1, 32>>>((float*)d_out);
}